// round 11
// baseline (speedup 1.0000x reference)
#include <cuda_runtime.h>
#include <cuda_fp16.h>

// Problem constants
#define H      1024
#define BB     2
#define CLS    30
#define EMBD   128
#define SEQ    1024
#define TSTEPS 1023      // n_seq - 1
#define G4     4096      // 4*H gate rows per layer

// Block partition: ALL gate rows of an element live in ONE warp.
#define NBL0   43        // L0 blocks: 24 elements x 4 gate rows = 96 rows
#define EL0    24
#define NBL1   86        // L1 blocks: 12 elements x 8 rows (4 Wih1 + 4 Whh1 interleaved) = 96
#define EL1    12
#define NB     (NBL0 + NBL1)   // 129 blocks, one per SM, co-resident
#define RPB    96
#define NT     192       // 6 warps; every warp is an mma warp

// SMEM layout: padded weight rows (conflict-free ldmatrix) + 4 padded h rows
#define RS     1032                    // halves per weight row (1024 + 8 pad)
#define RSB    (RS * 2)                // 2064 bytes
#define SWB    ((size_t)RPB * RSB)     // 198144 bytes of weights
#define HSB    (4 * RSB)               // 4 padded h rows (8256 bytes)
#define SMEM_TOTAL (SWB + HSB)         // 206400 bytes

// ---------------- persistent device state ----------------
__device__ float    d_condW0[BB * G4];                   // cond @ Wih0[:, :H]^T + b_ih0 + b_hh0
__device__ float    d_embproj[CLS * G4];                 // emb  @ Wih0[:, H:]^T per class
__device__ float    d_bias1[G4];                         // b_ih1 + b_hh1
__device__ __half   d_h0f16[2][BB * H];                  // double-buffered fp16 h0
__device__ __half   d_h1f16[2][BB * H];                  // double-buffered fp16 h1
__device__ float    d_h1hist[(size_t)TSTEPS * BB * H];   // layer-1 outputs (fp32) for CE
__device__ unsigned d_ctr[64];                           // [0]=L0 epoch counter, [32]=L1
__device__ float    d_nll[TSTEPS * BB];

// ---------------- helpers ----------------
__device__ __forceinline__ float tanhap(float x) {
    float y; asm("tanh.approx.f32 %0, %1;" : "=f"(y) : "f"(x)); return y;
}
__device__ __forceinline__ float sigap(float x) { return 0.5f * tanhap(0.5f * x) + 0.5f; }

// Aggregated-epoch wait: thread 0 polls the L0 counter, thread 32 polls the L1
// counter. Spin bound 2^16: a sync bug degrades to a wrong answer +
// diagnostics, never a container-killing hang (normal path: < 1e3 polls).
__device__ __forceinline__ void waitc(int t0, int t1, int tid) {
    if (tid == 0 && t0 > 0) {
        const unsigned* p = &d_ctr[0];
        unsigned v; unsigned spins = 0;
        do {
            asm volatile("ld.acquire.gpu.u32 %0, [%1];" : "=r"(v) : "l"(p) : "memory");
        } while ((int)v < t0 && ++spins < (1u << 16));
    } else if (tid == 32 && t1 > 0) {
        const unsigned* p = &d_ctr[32];
        unsigned v; unsigned spins = 0;
        do {
            asm volatile("ld.acquire.gpu.u32 %0, [%1];" : "=r"(v) : "l"(p) : "memory");
        } while ((int)v < t1 && ++spins < (1u << 16));
    }
    __syncthreads();
}

// ---------------- prep kernels ----------------
__global__ void k_reset() {
    int i = blockIdx.x * blockDim.x + threadIdx.x;
    if (i < 64) d_ctr[i] = 0u;
    if (i < 2 * BB * H) {
        ((__half*)d_h0f16)[i] = __float2half(0.f);
        ((__half*)d_h1f16)[i] = __float2half(0.f);
    }
}

// Coalesced prep: one warp per weight row, shfl reduction.
// Warp jobs [0,4096): condW0 (both batches) + bias1; [4096,8192): embproj.
__global__ void k_pre(const float* __restrict__ Wih0, const float* __restrict__ cond,
                      const float* __restrict__ emb,
                      const float* __restrict__ bih0, const float* __restrict__ bhh0,
                      const float* __restrict__ bih1, const float* __restrict__ bhh1) {
    int wg = (blockIdx.x * blockDim.x + threadIdx.x) >> 5;
    int lane = threadIdx.x & 31;
    if (wg < G4) {
        int j = wg;
        const float* wr = Wih0 + (size_t)j * 1152;
        float s0 = 0.f, s1 = 0.f;
#pragma unroll 8
        for (int i = 0; i < 32; ++i) {
            float w = wr[i * 32 + lane];
            s0 += w * cond[i * 32 + lane];
            s1 += w * cond[H + i * 32 + lane];
        }
#pragma unroll
        for (int off = 16; off > 0; off >>= 1) {
            s0 += __shfl_xor_sync(0xffffffffu, s0, off);
            s1 += __shfl_xor_sync(0xffffffffu, s1, off);
        }
        if (lane == 0) {
            float b = bih0[j] + bhh0[j];
            d_condW0[j]      = s0 + b;
            d_condW0[G4 + j] = s1 + b;
            d_bias1[j] = bih1[j] + bhh1[j];
        }
    } else if (wg < 2 * G4) {
        int j = wg - G4;
        const float* wr = Wih0 + (size_t)j * 1152 + H;
        float w0 = wr[lane], w1 = wr[32 + lane], w2 = wr[64 + lane], w3 = wr[96 + lane];
        for (int c = 0; c < CLS; ++c) {
            const float* eb = emb + c * EMBD;
            float s = w0 * eb[lane] + w1 * eb[32 + lane]
                    + w2 * eb[64 + lane] + w3 * eb[96 + lane];
#pragma unroll
            for (int off = 16; off > 0; off >>= 1)
                s += __shfl_xor_sync(0xffffffffu, s, off);
            if (lane == 0) d_embproj[c * G4 + j] = s;
        }
    }
}

// ---------------- persistent recurrent kernel ----------------
// L0 block: warp w owns rows 16w..16w+15 = elements 4w..4w+3 (4 gate rows each).
//   B cols 0-1 = h0[s-1] (batch 0,1); gate value = D[4e+g][bt].
// L1 block: warp w owns elements 2w,2w+1; per element 8 interleaved rows:
//   local rows 8p+{0..3} = Wih1 gates, 8p+{4..7} = Whh1 gates.
//   B cols 0-1 = h0[s] (batch 0,1), cols 2-3 = h1[s-1] (batch 0,1).
//   gate = D[8p+g][bt] (Wih1*h0) + D[8p+4+g][2+bt] (Whh1*h1p) + bias.
// Epilogue is a pure in-warp shuffle gather (no SMEM gres, one fewer barrier).
// mma.sync m16n8k16 fp32-acc; A k-steps [0,32) preloaded in registers.
// Epochs: L0@s needs ctr0>=43s, ctr1>=86(s-1); L1@s needs ctr0>=43(s+1), ctr1>=86s.
__global__ void __launch_bounds__(NT, 1)
k_recur(const long long* __restrict__ ids,
        const float* __restrict__ Whh0,
        const float* __restrict__ Wih1,
        const float* __restrict__ Whh1) {
    extern __shared__ char smem[];
    __half* sw  = (__half*)smem;
    __half* hsm = (__half*)(smem + SWB);
    const unsigned smem_u32 = (unsigned)__cvta_generic_to_shared(smem);
    const unsigned hsm_u32  = smem_u32 + (unsigned)SWB;

    const int tid = threadIdx.x, bk = blockIdx.x;
    const int lane = tid & 31, warp = tid >> 5;
    const bool isL1 = (bk >= NBL0);
    const int lb = isL1 ? (bk - NBL0) : bk;
    const int ebase = isL1 ? lb * EL1 : lb * EL0;

    // ---- prologue: gather fp32 weight rows -> fp16 SMEM, padded stride (once) ----
    for (int i = tid; i < RPB * 256; i += NT) {
        int s = i >> 8, c = i & 255;     // c = float4 index within the 1024-wide row
        int g, e; const float* src;
        if (!isL1) { g = s & 3; e = ebase + (s >> 2); src = Whh0; }
        else {
            int j = s >> 3, part = (s >> 2) & 1;
            g = s & 3; e = ebase + j;
            src = part ? Whh1 : Wih1;
        }
        __half2 out0, out1;
        if (e < H) {
            float4 v = *(const float4*)(src + (size_t)(g * 1024 + e) * H + c * 4);
            out0 = __floats2half2_rn(v.x, v.y);
            out1 = __floats2half2_rn(v.z, v.w);
        } else {
            out0 = __floats2half2_rn(0.f, 0.f); out1 = out0;
        }
        uint2 packed;
        packed.x = *reinterpret_cast<unsigned*>(&out0);
        packed.y = *reinterpret_cast<unsigned*>(&out1);
        *(uint2*)(sw + (size_t)s * RS + c * 4) = packed;
    }

    // ---- per-lane elementwise ownership (in-warp epilogue) ----
    const int bt = lane & 1;
    const int jt = !isL1 ? (4 * warp + ((lane >> 1) & 3)) : (2 * warp + ((lane >> 1) & 1));
    const int et = ebase + jt;
    const bool own = !isL1 ? (lane < 8) : (lane < 4);
    const bool ok = own && (et < H);
    float cw0 = 0, cw1 = 0, cw2 = 0, cw3 = 0;
    if (ok) {
        if (!isL1) {
            const float* cw = d_condW0 + bt * G4 + et;
            cw0 = cw[0]; cw1 = cw[1024]; cw2 = cw[2048]; cw3 = cw[3072];
        } else {
            cw0 = d_bias1[et];        cw1 = d_bias1[et + 1024];
            cw2 = d_bias1[et + 2048]; cw3 = d_bias1[et + 3072];
        }
    }
    float cst = 0.f;   // cell state, register-resident for the whole sequence

    // ---- mma operand addressing (constant across steps) ----
    const int arow = lane & 15;
    const unsigned a_addr0 = smem_u32 + (unsigned)((warp * 16 + arow) * RSB + ((lane >> 4) * 16));
    const int nidx = lane >> 2;
    const int nrows = isL1 ? 4 : 2;
    const bool nreal = (nidx < nrows);
    const unsigned b_addr0 = hsm_u32 + (unsigned)((nreal ? nidx : 0) * RSB + (lane & 3) * 4);
    __syncthreads();   // SMEM weights ready

    // ---- preload step-invariant A fragments for k-steps [0,32) into registers ----
    unsigned ar0[32], ar1[32], ar2[32], ar3[32];
#pragma unroll
    for (int k = 0; k < 32; ++k) {
        asm volatile("ldmatrix.sync.aligned.m8n8.x4.shared.b16 {%0,%1,%2,%3}, [%4];"
                     : "=r"(ar0[k]), "=r"(ar1[k]), "=r"(ar2[k]), "=r"(ar3[k])
                     : "r"(a_addr0 + k * 32));
    }

    for (int s = 0; s < TSTEPS; ++s) {
        const int sb = s & 1, pb = (s + 1) & 1;

        // per-step elementwise prefetch (token projection, L0 only) — before the wait
        float ep0 = 0, ep1 = 0, ep2 = 0, ep3 = 0;
        if (ok && !isL1) {
            int tok = (int)ids[bt * SEQ + s];
            const float* ep = d_embproj + tok * G4 + et;
            ep0 = ep[0]; ep1 = ep[1024]; ep2 = ep[2048]; ep3 = ep[3072];
        }

        // epoch waits (cross-group slack absorbs jitter)
        if (!isL1) waitc(NBL0 * s,       NBL1 * (s - 1), tid);
        else       waitc(NBL0 * (s + 1), NBL1 * s,       tid);

        // stage fp16 h into padded SMEM rows
        if (!isL1) {                                   // rows 0-1 <- h0[s-1]
            const __half* src = d_h0f16[pb];
            for (int i = tid; i < 256; i += NT) {
                int row = i >> 7, col = (i & 127) * 8;
                *(uint4*)(hsm + row * RS + col) = *(const uint4*)(src + row * H + col);
            }
        } else {                                       // rows 0-1 <- h0[s]; 2-3 <- h1[s-1]
            const __half* s0p = d_h0f16[sb];
            const __half* s1p = d_h1f16[pb];
            for (int i = tid; i < 512; i += NT) {
                int row = i >> 7, col = (i & 127) * 8;
                const __half* src = (row < 2) ? s0p : s1p;
                *(uint4*)(hsm + row * RS + col) = *(const uint4*)(src + (row & 1) * H + col);
            }
        }
        __syncthreads();   // h staged

        // ---- dot phase: mma.sync, 16 rows per warp, 4 accumulator chains ----
        float d0[4] = {0,0,0,0}, d1[4] = {0,0,0,0};
        float d2[4] = {0,0,0,0}, d3[4] = {0,0,0,0};
        // SMEM half: k-steps [32,64) via ldmatrix
#pragma unroll
        for (int k = 0; k < 32; ++k) {
            unsigned a0, a1, a2, a3;
            asm volatile("ldmatrix.sync.aligned.m8n8.x4.shared.b16 {%0,%1,%2,%3}, [%4];"
                         : "=r"(a0), "=r"(a1), "=r"(a2), "=r"(a3)
                         : "r"(a_addr0 + (32 + k) * 32));
            unsigned b0 = 0, b1 = 0;
            if (nreal) {
                asm volatile("ld.shared.u32 %0, [%1];" : "=r"(b0) : "r"(b_addr0 + (32 + k) * 32));
                asm volatile("ld.shared.u32 %0, [%1];" : "=r"(b1) : "r"(b_addr0 + (32 + k) * 32 + 16));
            }
            const int ch = k & 3;
            asm volatile("mma.sync.aligned.m16n8k16.row.col.f32.f16.f16.f32 "
                         "{%0,%1,%2,%3}, {%4,%5,%6,%7}, {%8,%9}, {%0,%1,%2,%3};"
                         : "+f"(d0[ch]), "+f"(d1[ch]), "+f"(d2[ch]), "+f"(d3[ch])
                         : "r"(a0), "r"(a1), "r"(a2), "r"(a3), "r"(b0), "r"(b1));
        }
        // register half: k-steps [0,32), A already resident
#pragma unroll
        for (int k = 0; k < 32; ++k) {
            unsigned b0 = 0, b1 = 0;
            if (nreal) {
                asm volatile("ld.shared.u32 %0, [%1];" : "=r"(b0) : "r"(b_addr0 + k * 32));
                asm volatile("ld.shared.u32 %0, [%1];" : "=r"(b1) : "r"(b_addr0 + k * 32 + 16));
            }
            const int ch = k & 3;
            asm volatile("mma.sync.aligned.m16n8k16.row.col.f32.f16.f16.f32 "
                         "{%0,%1,%2,%3}, {%4,%5,%6,%7}, {%8,%9}, {%0,%1,%2,%3};"
                         : "+f"(d0[ch]), "+f"(d1[ch]), "+f"(d2[ch]), "+f"(d3[ch])
                         : "r"(ar0[k]), "r"(ar1[k]), "r"(ar2[k]), "r"(ar3[k]),
                           "r"(b0), "r"(b1));
        }
        float c0 = d0[0] + d0[1] + d0[2] + d0[3];
        float c1 = d1[0] + d1[1] + d1[2] + d1[3];
        float c2 = d2[0] + d2[1] + d2[2] + d2[3];
        float c3 = d3[0] + d3[1] + d3[2] + d3[3];
        // D mapping (validated R8): thread holds rows (lane>>2, +8), cols 2(lane&3), +1
        // as (c0,c1) lower-row pair and (c2,c3) upper-row pair.

        // ---- in-warp epilogue: shuffle-gather gates, LSTM cell, store h ----
        if (!isL1) {
            int eL = (lane >> 1) & 3;
            bool hiRow = (eL >= 2);
            float v[4];
#pragma unroll
            for (int g = 0; g < 4; ++g) {
                int src = ((4 * eL + g) & 7) * 4;       // col pair 0 -> lane offset 0
                float s0v = __shfl_sync(0xffffffffu, c0, src);
                float s1v = __shfl_sync(0xffffffffu, c1, src);
                float s2v = __shfl_sync(0xffffffffu, c2, src);
                float s3v = __shfl_sync(0xffffffffu, c3, src);
                float lo = bt ? s1v : s0v;
                float hi = bt ? s3v : s2v;
                v[g] = hiRow ? hi : lo;
            }
            if (ok) {
                float gi = v[0] + cw0 + ep0;
                float gf = v[1] + cw1 + ep1;
                float gg = v[2] + cw2 + ep2;
                float go = v[3] + cw3 + ep3;
                cst = sigap(gf) * cst + sigap(gi) * tanhap(gg);
                float h = sigap(go) * tanhap(cst);
                d_h0f16[sb][bt * H + et] = __float2half(h);
            }
        } else {
            int pL = (lane >> 1) & 1;
            float va[4], vb[4];
#pragma unroll
            for (int g = 0; g < 4; ++g) {
                int srcA = g * 4;                       // Wih1 row 8p+g, cols 0-1
                int srcB = (4 + g) * 4 + 1;             // Whh1 row 8p+4+g, cols 2-3
                float a0 = __shfl_sync(0xffffffffu, c0, srcA);
                float a1 = __shfl_sync(0xffffffffu, c1, srcA);
                float a2 = __shfl_sync(0xffffffffu, c2, srcA);
                float a3 = __shfl_sync(0xffffffffu, c3, srcA);
                float b0v = __shfl_sync(0xffffffffu, c0, srcB);
                float b1v = __shfl_sync(0xffffffffu, c1, srcB);
                float b2v = __shfl_sync(0xffffffffu, c2, srcB);
                float b3v = __shfl_sync(0xffffffffu, c3, srcB);
                va[g] = pL ? (bt ? a3 : a2) : (bt ? a1 : a0);
                vb[g] = pL ? (bt ? b3v : b2v) : (bt ? b1v : b0v);
            }
            if (ok) {
                float gi = va[0] + vb[0] + cw0;
                float gf = va[1] + vb[1] + cw1;
                float gg = va[2] + vb[2] + cw2;
                float go = va[3] + vb[3] + cw3;
                cst = sigap(gf) * cst + sigap(gi) * tanhap(gg);
                float h = sigap(go) * tanhap(cst);
                d_h1f16[sb][bt * H + et] = __float2half(h);
                d_h1hist[(size_t)s * (BB * H) + bt * H + et] = h;
            }
        }
        __syncthreads();   // all h writes done before publish; also protects hsm

        if (tid == 0) {
            const unsigned* ctr = isL1 ? &d_ctr[32] : &d_ctr[0];
            asm volatile("red.release.gpu.global.add.u32 [%0], %1;"
                         :: "l"(ctr), "r"(1u) : "memory");
        }
    }
}

// ---------------- CE kernels ----------------
__global__ void k_ce(const long long* __restrict__ ids,
                     const float* __restrict__ fcw, const float* __restrict__ fcb) {
    __shared__ float hs[H];
    __shared__ float lg[32];
    const int m = blockIdx.x;           // 0..2045
    const int b = m & 1, t = m >> 1;
    const int tid = threadIdx.x, lane = tid & 31, warp = tid >> 5;

    const float* hp = d_h1hist + (size_t)t * BB * H + b * H;
    for (int i = tid; i < H; i += 256) hs[i] = hp[i];
    __syncthreads();

    for (int c = warp; c < CLS; c += 8) {
        const float* wr = fcw + c * H;
        float s = 0.f;
        for (int k = lane; k < H; k += 32) s += wr[k] * hs[k];
#pragma unroll
        for (int off = 16; off > 0; off >>= 1) s += __shfl_xor_sync(0xffffffffu, s, off);
        if (lane == 0) lg[c] = s + fcb[c];
    }
    __syncthreads();

    if (tid == 0) {
        float mx = -1e30f;
        for (int c = 0; c < CLS; ++c) mx = fmaxf(mx, lg[c]);
        float se = 0.f;
        for (int c = 0; c < CLS; ++c) se += expf(lg[c] - mx);
        float lse = mx + logf(se);
        int tgt = (int)ids[b * SEQ + t + 1];
        d_nll[m] = lse - lg[tgt];
    }
}

__global__ void k_loss(const float* __restrict__ mask, float* __restrict__ out) {
    __shared__ float s1s[256], s2s[256];
    const int tid = threadIdx.x;
    float sn = 0.f, sm = 0.f;
    for (int i = tid; i < TSTEPS * BB; i += 256) sn += d_nll[i];
    for (int i = tid; i < BB * TSTEPS; i += 256) {
        int b = i / TSTEPS, t = i % TSTEPS;
        sm += mask[b * SEQ + t + 1];
    }
    s1s[tid] = sn; s2s[tid] = sm;
    __syncthreads();
    for (int o = 128; o > 0; o >>= 1) {
        if (tid < o) { s1s[tid] += s1s[tid + o]; s2s[tid] += s2s[tid + o]; }
        __syncthreads();
    }
    if (tid == 0) {
        float ce = s1s[0] / (float)(TSTEPS * BB);
        float masked = ce * s2s[0] / s2s[0];   // matches reference (incl. mask==0 -> NaN)
        out[0] = ce + masked;
    }
}

// ---------------- launch ----------------
extern "C" void kernel_launch(void* const* d_in, const int* in_sizes, int n_in,
                              void* d_out, int out_size) {
    const long long* ids  = (const long long*)d_in[0];
    const float* mask     = (const float*)d_in[1];
    const float* cond     = (const float*)d_in[2];
    const float* emb      = (const float*)d_in[3];
    const float* Wih0     = (const float*)d_in[4];
    const float* Whh0     = (const float*)d_in[5];
    const float* bih0     = (const float*)d_in[6];
    const float* bhh0     = (const float*)d_in[7];
    const float* Wih1     = (const float*)d_in[8];
    const float* Whh1     = (const float*)d_in[9];
    const float* bih1     = (const float*)d_in[10];
    const float* bhh1     = (const float*)d_in[11];
    const float* fcw      = (const float*)d_in[12];
    const float* fcb      = (const float*)d_in[13];

    static bool init = false;
    if (!init) {
        cudaFuncSetAttribute(k_recur, cudaFuncAttributeMaxDynamicSharedMemorySize,
                             (int)SMEM_TOTAL);
        init = true;
    }

    k_reset<<<32, 256>>>();
    k_pre<<<(2 * G4 * 32 + 255) / 256, 256>>>(Wih0, cond, emb, bih0, bhh0, bih1, bhh1);
    k_recur<<<NB, NT, SMEM_TOTAL>>>(ids, Whh0, Wih1, Whh1);
    k_ce<<<TSTEPS * BB, 256>>>(ids, fcw, fcb);
    k_loss<<<1, 256>>>(mask, (float*)d_out);
}

// round 12
// speedup vs baseline: 1.2265x; 1.2265x over previous
#include <cuda_runtime.h>
#include <cuda_fp16.h>

// Problem constants
#define H      1024
#define BB     2
#define CLS    30
#define EMBD   128
#define SEQ    1024
#define TSTEPS 1023      // n_seq - 1
#define G4     4096      // 4*H gate rows per layer

// Block partition: gate rows of an element live in ONE block.
#define NBL0   43        // L0 blocks: 24 elements x 4 gate rows = 96 rows
#define EL0    24
#define NBL1   86        // L1 blocks: 12 elements x 8 rows (4 Wih1 + 4 Whh1) = 96
#define EL1    12
#define NB     (NBL0 + NBL1)   // 129 blocks, one per SM, co-resident
#define RPB    96

// SMEM layout: padded weight rows (conflict-free ldmatrix), h staging, gate results
#define RS     1032                    // halves per weight row (1024 + 8 pad)
#define RSB    (RS * 2)                // 2064 bytes
#define SWB    ((size_t)RPB * RSB)     // 198144 bytes of weights
#define HSB    (4 * RSB)               // 4 padded h rows (8256 bytes)
#define SMEM_TOTAL (SWB + HSB + RPB * 2 * sizeof(float))   // + gres = 207168

// ---------------- persistent device state ----------------
__device__ float    d_condW0[BB * G4];                   // cond @ Wih0[:, :H]^T + b_ih0 + b_hh0
__device__ float    d_embproj[CLS * G4];                 // emb  @ Wih0[:, H:]^T per class
__device__ float    d_bias1[G4];                         // b_ih1 + b_hh1
// Tagged h exchange: word = {lo16: fp16 h, hi16: step tag (writer step + 1)}
__device__ __align__(16) unsigned d_h0t[2][BB * H];      // double-buffered tagged h0
__device__ __align__(16) unsigned d_h1t[2][BB * H];      // double-buffered tagged h1
__device__ float    d_h1hist[(size_t)TSTEPS * BB * H];   // layer-1 outputs (fp32) for CE
__device__ unsigned d_ctr[64];                           // staged-epoch ctrs: [0]=L0, [32]=L1
__device__ float    d_nll[TSTEPS * BB];

// ---------------- helpers ----------------
__device__ __forceinline__ float tanhap(float x) {
    float y; asm("tanh.approx.f32 %0, %1;" : "=f"(y) : "f"(x)); return y;
}
__device__ __forceinline__ float sigap(float x) { return 0.5f * tanhap(0.5f * x) + 0.5f; }

// Backpressure wait on STAGED epoch counters (published right after staging, so
// these carry a full step of slack and are normally pre-satisfied).
// Bounded spin: a sync bug degrades to a wrong answer, never a hang.
__device__ __forceinline__ void waitc(int t0, int t1, int tid) {
    if (tid == 0 && t0 > 0) {
        const unsigned* p = &d_ctr[0];
        unsigned v; unsigned spins = 0;
        do {
            asm volatile("ld.acquire.gpu.u32 %0, [%1];" : "=r"(v) : "l"(p) : "memory");
        } while ((int)v < t0 && ++spins < (1u << 16));
    } else if (tid == 32 && t1 > 0) {
        const unsigned* p = &d_ctr[32];
        unsigned v; unsigned spins = 0;
        do {
            asm volatile("ld.acquire.gpu.u32 %0, [%1];" : "=r"(v) : "l"(p) : "memory");
        } while ((int)v < t1 && ++spins < (1u << 16));
    }
    __syncthreads();
}

// Tagged uint4 load with retry-until-fresh (detection fused with the data load).
__device__ __forceinline__ uint4 ld_tagged(const unsigned* src, unsigned exp) {
    uint4 w; unsigned spins = 0; bool okf;
    do {
        asm volatile("ld.relaxed.gpu.global.v4.u32 {%0,%1,%2,%3}, [%4];"
                     : "=r"(w.x), "=r"(w.y), "=r"(w.z), "=r"(w.w) : "l"(src));
        okf = ((w.x >> 16) == exp) & ((w.y >> 16) == exp)
            & ((w.z >> 16) == exp) & ((w.w >> 16) == exp);
    } while (!okf && ++spins < (1u << 16));
    return w;
}

// ---------------- prep kernels ----------------
__global__ void k_reset() {
    int i = blockIdx.x * blockDim.x + threadIdx.x;
    if (i < 64) d_ctr[i] = 0u;
    if (i < 2 * BB * H) {                 // tag 0 == "step -1", h = +0
        ((unsigned*)d_h0t)[i] = 0u;
        ((unsigned*)d_h1t)[i] = 0u;
    }
}

// Coalesced prep: one warp per weight row, shfl reduction.
__global__ void k_pre(const float* __restrict__ Wih0, const float* __restrict__ cond,
                      const float* __restrict__ emb,
                      const float* __restrict__ bih0, const float* __restrict__ bhh0,
                      const float* __restrict__ bih1, const float* __restrict__ bhh1) {
    int wg = (blockIdx.x * blockDim.x + threadIdx.x) >> 5;
    int lane = threadIdx.x & 31;
    if (wg < G4) {
        int j = wg;
        const float* wr = Wih0 + (size_t)j * 1152;
        float s0 = 0.f, s1 = 0.f;
#pragma unroll 8
        for (int i = 0; i < 32; ++i) {
            float w = wr[i * 32 + lane];
            s0 += w * cond[i * 32 + lane];
            s1 += w * cond[H + i * 32 + lane];
        }
#pragma unroll
        for (int off = 16; off > 0; off >>= 1) {
            s0 += __shfl_xor_sync(0xffffffffu, s0, off);
            s1 += __shfl_xor_sync(0xffffffffu, s1, off);
        }
        if (lane == 0) {
            float b = bih0[j] + bhh0[j];
            d_condW0[j]      = s0 + b;
            d_condW0[G4 + j] = s1 + b;
            d_bias1[j] = bih1[j] + bhh1[j];
        }
    } else if (wg < 2 * G4) {
        int j = wg - G4;
        const float* wr = Wih0 + (size_t)j * 1152 + H;
        float w0 = wr[lane], w1 = wr[32 + lane], w2 = wr[64 + lane], w3 = wr[96 + lane];
        for (int c = 0; c < CLS; ++c) {
            const float* eb = emb + c * EMBD;
            float s = w0 * eb[lane] + w1 * eb[32 + lane]
                    + w2 * eb[64 + lane] + w3 * eb[96 + lane];
#pragma unroll
            for (int off = 16; off > 0; off >>= 1)
                s += __shfl_xor_sync(0xffffffffu, s, off);
            if (lane == 0) d_embproj[c * G4 + j] = s;
        }
    }
}

// ---------------- persistent recurrent kernel (R10 skeleton + tagged exchange) --
// L0 block bk<NBL0: elements e = bk*24+j; weight slot s = j*4+g -> Whh0[g*1024+e]
// L1 block: elements e = lb*12+j; slots [0,48): Wih1 (input h0[s]),
//                                 slots [48,96): Whh1 (input h1[s-1])
// Dot: D[96x2] = W * h via mma.sync m16n8k16 fp32-acc; A ksteps [0,32) in regs.
// Availability: tag-in-payload (reader polls the h words themselves).
// Backpressure: staged counters. L0@s: ctrS0>=43s, ctrS1>=86(s-1); L1@s: ctrS1>=86s.
__global__ void __launch_bounds__(256, 1)
k_recur(const long long* __restrict__ ids,
        const float* __restrict__ Whh0,
        const float* __restrict__ Wih1,
        const float* __restrict__ Whh1) {
    extern __shared__ char smem[];
    __half* sw  = (__half*)smem;
    __half* hsm = (__half*)(smem + SWB);
    float (*gres)[2] = (float(*)[2])(smem + SWB + HSB);
    const unsigned smem_u32 = (unsigned)__cvta_generic_to_shared(smem);
    const unsigned hsm_u32  = smem_u32 + (unsigned)SWB;

    const int tid = threadIdx.x, bk = blockIdx.x;
    const int lane = tid & 31, warp = tid >> 5;
    const bool isL1 = (bk >= NBL0);
    const int lb = isL1 ? (bk - NBL0) : bk;
    const int ebase = isL1 ? lb * EL1 : lb * EL0;

    // ---- prologue: gather fp32 weight rows -> fp16 SMEM, padded stride (once) ----
    for (int i = tid; i < RPB * 256; i += 256) {
        int s = i >> 8, c = i & 255;
        int g, e; const float* src;
        if (!isL1)      { g = s & 3;        e = ebase + (s >> 2);        src = Whh0; }
        else if (s < 48){ g = s & 3;        e = ebase + (s >> 2);        src = Wih1; }
        else            { int s2 = s - 48; g = s2 & 3; e = ebase + (s2 >> 2); src = Whh1; }
        __half2 out0, out1;
        if (e < H) {
            float4 v = *(const float4*)(src + (size_t)(g * 1024 + e) * H + c * 4);
            out0 = __floats2half2_rn(v.x, v.y);
            out1 = __floats2half2_rn(v.z, v.w);
        } else {
            out0 = __floats2half2_rn(0.f, 0.f); out1 = out0;
        }
        uint2 packed;
        packed.x = *reinterpret_cast<unsigned*>(&out0);
        packed.y = *reinterpret_cast<unsigned*>(&out1);
        *(uint2*)(sw + (size_t)s * RS + c * 4) = packed;
    }

    // ---- elementwise task setup (thread tid -> (j = tid/2, batch = tid&1)) ----
    const int nel = isL1 ? EL1 : EL0;
    const int jt = tid >> 1, bt = tid & 1;
    const int et = ebase + jt;
    const bool task = (jt < nel) && (et < H);
    float cw0 = 0, cw1 = 0, cw2 = 0, cw3 = 0;
    if (task) {
        if (!isL1) {
            const float* cw = d_condW0 + bt * G4 + et;
            cw0 = cw[0]; cw1 = cw[1024]; cw2 = cw[2048]; cw3 = cw[3072];
        } else {
            cw0 = d_bias1[et];        cw1 = d_bias1[et + 1024];
            cw2 = d_bias1[et + 2048]; cw3 = d_bias1[et + 3072];
        }
    }
    float cst = 0.f;   // cell state, register-resident for the whole sequence

    // ---- mma operand addressing (constant across steps) ----
    const bool mmaw = (warp < 6);
    const int arow = lane & 15;
    const unsigned a_addr0 = smem_u32 + (unsigned)((warp * 16 + arow) * RSB + ((lane >> 4) * 16));
    const int nidx = lane >> 2;
    const bool nreal = (nidx < 2);
    const int hrowbase = (isL1 && warp >= 3) ? 2 : 0;   // L1 warps 3-5 read h1p rows
    const unsigned b_addr0 = hsm_u32 + (unsigned)((hrowbase + (nreal ? nidx : 0)) * RSB
                                                  + (lane & 3) * 4);
    __syncthreads();   // SMEM weights ready

    // ---- preload step-invariant A fragments for k-steps [0,32) into registers ----
    unsigned ar0[32], ar1[32], ar2[32], ar3[32];
    if (mmaw) {
#pragma unroll
        for (int k = 0; k < 32; ++k) {
            asm volatile("ldmatrix.sync.aligned.m8n8.x4.shared.b16 {%0,%1,%2,%3}, [%4];"
                         : "=r"(ar0[k]), "=r"(ar1[k]), "=r"(ar2[k]), "=r"(ar3[k])
                         : "r"(a_addr0 + k * 32));
        }
    }

    for (int s = 0; s < TSTEPS; ++s) {
        const int sb = s & 1, pb = (s + 1) & 1;
        const unsigned tagP = (unsigned)s;        // h{0,1}[s-1] tag
        const unsigned tagC = (unsigned)(s + 1);  // h0[s] tag (written this step)

        // per-step elementwise prefetch (token projection, L0 only) — before waits
        float ep0 = 0, ep1 = 0, ep2 = 0, ep3 = 0;
        if (task && !isL1) {
            int tok = (int)ids[bt * SEQ + s];
            const float* ep = d_embproj + tok * G4 + et;
            ep0 = ep[0]; ep1 = ep[1024]; ep2 = ep[2048]; ep3 = ep[3072];
        }

        // backpressure waits (staged counters; carry 1-step slack, rarely binding)
        if (!isL1) waitc(NBL0 * s, NBL1 * (s - 1), tid);
        else       waitc(0,        NBL1 * s,       tid);

        // stage h: tagged loads (availability detection fused with the load)
        if (!isL1) {                                   // rows 0-1 <- h0[s-1]
            for (int i = tid; i < 512; i += 256) {
                uint4 w = ld_tagged(d_h0t[pb] + i * 4, tagP);
                int word = i * 4, row = word >> 10, col = word & 1023;
                uint2 p;
                p.x = (w.x & 0xFFFFu) | (w.y << 16);
                p.y = (w.z & 0xFFFFu) | (w.w << 16);
                *(uint2*)(hsm + row * RS + col) = p;
            }
        } else {                                       // rows 0-1 <- h0[s]; 2-3 <- h1[s-1]
            for (int i = tid; i < 1024; i += 256) {
                const bool second = (i >= 512);
                const int j = second ? (i - 512) : i;
                const unsigned* src = (second ? d_h1t[pb] : d_h0t[sb]) + j * 4;
                uint4 w = ld_tagged(src, second ? tagP : tagC);
                int word = j * 4, row = (word >> 10) + (second ? 2 : 0), col = word & 1023;
                uint2 p;
                p.x = (w.x & 0xFFFFu) | (w.y << 16);
                p.y = (w.z & 0xFFFFu) | (w.w << 16);
                *(uint2*)(hsm + row * RS + col) = p;
            }
        }
        __syncthreads();   // hsm ready

        // publish staged-epoch (backpressure release for writers) — fire and forget
        if (tid == 0) {
            const unsigned* ctr = isL1 ? &d_ctr[32] : &d_ctr[0];
            asm volatile("red.release.gpu.global.add.u32 [%0], %1;"
                         :: "l"(ctr), "r"(1u) : "memory");
        }

        // ---- dot phase: mma.sync, 16 rows per warp, 4 accumulator chains ----
        if (mmaw) {
            float d0[4] = {0,0,0,0}, d1[4] = {0,0,0,0};
            float d2[4] = {0,0,0,0}, d3[4] = {0,0,0,0};
#pragma unroll
            for (int k = 0; k < 32; ++k) {
                unsigned a0, a1, a2, a3;
                asm volatile("ldmatrix.sync.aligned.m8n8.x4.shared.b16 {%0,%1,%2,%3}, [%4];"
                             : "=r"(a0), "=r"(a1), "=r"(a2), "=r"(a3)
                             : "r"(a_addr0 + (32 + k) * 32));
                unsigned b0 = 0, b1 = 0;
                if (nreal) {
                    asm volatile("ld.shared.u32 %0, [%1];" : "=r"(b0) : "r"(b_addr0 + (32 + k) * 32));
                    asm volatile("ld.shared.u32 %0, [%1];" : "=r"(b1) : "r"(b_addr0 + (32 + k) * 32 + 16));
                }
                const int ch = k & 3;
                asm volatile("mma.sync.aligned.m16n8k16.row.col.f32.f16.f16.f32 "
                             "{%0,%1,%2,%3}, {%4,%5,%6,%7}, {%8,%9}, {%0,%1,%2,%3};"
                             : "+f"(d0[ch]), "+f"(d1[ch]), "+f"(d2[ch]), "+f"(d3[ch])
                             : "r"(a0), "r"(a1), "r"(a2), "r"(a3), "r"(b0), "r"(b1));
            }
#pragma unroll
            for (int k = 0; k < 32; ++k) {
                unsigned b0 = 0, b1 = 0;
                if (nreal) {
                    asm volatile("ld.shared.u32 %0, [%1];" : "=r"(b0) : "r"(b_addr0 + k * 32));
                    asm volatile("ld.shared.u32 %0, [%1];" : "=r"(b1) : "r"(b_addr0 + k * 32 + 16));
                }
                const int ch = k & 3;
                asm volatile("mma.sync.aligned.m16n8k16.row.col.f32.f16.f16.f32 "
                             "{%0,%1,%2,%3}, {%4,%5,%6,%7}, {%8,%9}, {%0,%1,%2,%3};"
                             : "+f"(d0[ch]), "+f"(d1[ch]), "+f"(d2[ch]), "+f"(d3[ch])
                             : "r"(ar0[k]), "r"(ar1[k]), "r"(ar2[k]), "r"(ar3[k]),
                               "r"(b0), "r"(b1));
            }
            if ((lane & 3) == 0) {
                const int g = lane >> 2;
                const int r = warp * 16 + g;
                float2 lo = make_float2(d0[0] + d0[1] + d0[2] + d0[3],
                                        d1[0] + d1[1] + d1[2] + d1[3]);
                float2 hi = make_float2(d2[0] + d2[1] + d2[2] + d2[3],
                                        d3[0] + d3[1] + d3[2] + d3[3]);
                *(float2*)&gres[r][0]     = lo;   // rows r   : batch 0,1
                *(float2*)&gres[r + 8][0] = hi;   // rows r+8 : batch 0,1
            }
        }
        __syncthreads();   // gres visible block-wide

        // ---- elementwise phase (block-local gate gather, tagged h publish) ----
        if (task) {
            const int j4 = jt * 4;
            float gi, gf, gg, go;
            if (!isL1) {
                gi = gres[j4 + 0][bt] + cw0 + ep0;
                gf = gres[j4 + 1][bt] + cw1 + ep1;
                gg = gres[j4 + 2][bt] + cw2 + ep2;
                go = gres[j4 + 3][bt] + cw3 + ep3;
            } else {
                gi = gres[j4 + 0][bt] + gres[48 + j4 + 0][bt] + cw0;
                gf = gres[j4 + 1][bt] + gres[48 + j4 + 1][bt] + cw1;
                gg = gres[j4 + 2][bt] + gres[48 + j4 + 2][bt] + cw2;
                go = gres[j4 + 3][bt] + gres[48 + j4 + 3][bt] + cw3;
            }
            cst = sigap(gf) * cst + sigap(gi) * tanhap(gg);
            float h = sigap(go) * tanhap(cst);
            unsigned hw = (unsigned)__half_as_ushort(__float2half(h)) | (tagC << 16);
            if (!isL1) {
                asm volatile("st.relaxed.gpu.global.u32 [%0], %1;"
                             :: "l"(&d_h0t[sb][bt * H + et]), "r"(hw) : "memory");
            } else {
                asm volatile("st.relaxed.gpu.global.u32 [%0], %1;"
                             :: "l"(&d_h1t[sb][bt * H + et]), "r"(hw) : "memory");
                d_h1hist[(size_t)s * (BB * H) + bt * H + et] = h;
            }
        }
        // no end-of-step publish/sync: availability is via tags; the next
        // iteration's waitc __syncthreads isolates hsm/gres reuse.
    }
}

// ---------------- CE kernels ----------------
__global__ void k_ce(const long long* __restrict__ ids,
                     const float* __restrict__ fcw, const float* __restrict__ fcb) {
    __shared__ float hs[H];
    __shared__ float lg[32];
    const int m = blockIdx.x;           // 0..2045
    const int b = m & 1, t = m >> 1;
    const int tid = threadIdx.x, lane = tid & 31, warp = tid >> 5;

    const float* hp = d_h1hist + (size_t)t * BB * H + b * H;
    for (int i = tid; i < H; i += 256) hs[i] = hp[i];
    __syncthreads();

    for (int c = warp; c < CLS; c += 8) {
        const float* wr = fcw + c * H;
        float s = 0.f;
        for (int k = lane; k < H; k += 32) s += wr[k] * hs[k];
#pragma unroll
        for (int off = 16; off > 0; off >>= 1) s += __shfl_xor_sync(0xffffffffu, s, off);
        if (lane == 0) lg[c] = s + fcb[c];
    }
    __syncthreads();

    if (tid == 0) {
        float mx = -1e30f;
        for (int c = 0; c < CLS; ++c) mx = fmaxf(mx, lg[c]);
        float se = 0.f;
        for (int c = 0; c < CLS; ++c) se += expf(lg[c] - mx);
        float lse = mx + logf(se);
        int tgt = (int)ids[b * SEQ + t + 1];
        d_nll[m] = lse - lg[tgt];
    }
}

__global__ void k_loss(const float* __restrict__ mask, float* __restrict__ out) {
    __shared__ float s1s[256], s2s[256];
    const int tid = threadIdx.x;
    float sn = 0.f, sm = 0.f;
    for (int i = tid; i < TSTEPS * BB; i += 256) sn += d_nll[i];
    for (int i = tid; i < BB * TSTEPS; i += 256) {
        int b = i / TSTEPS, t = i % TSTEPS;
        sm += mask[b * SEQ + t + 1];
    }
    s1s[tid] = sn; s2s[tid] = sm;
    __syncthreads();
    for (int o = 128; o > 0; o >>= 1) {
        if (tid < o) { s1s[tid] += s1s[tid + o]; s2s[tid] += s2s[tid + o]; }
        __syncthreads();
    }
    if (tid == 0) {
        float ce = s1s[0] / (float)(TSTEPS * BB);
        float masked = ce * s2s[0] / s2s[0];   // matches reference (incl. mask==0 -> NaN)
        out[0] = ce + masked;
    }
}

// ---------------- launch ----------------
extern "C" void kernel_launch(void* const* d_in, const int* in_sizes, int n_in,
                              void* d_out, int out_size) {
    const long long* ids  = (const long long*)d_in[0];
    const float* mask     = (const float*)d_in[1];
    const float* cond     = (const float*)d_in[2];
    const float* emb      = (const float*)d_in[3];
    const float* Wih0     = (const float*)d_in[4];
    const float* Whh0     = (const float*)d_in[5];
    const float* bih0     = (const float*)d_in[6];
    const float* bhh0     = (const float*)d_in[7];
    const float* Wih1     = (const float*)d_in[8];
    const float* Whh1     = (const float*)d_in[9];
    const float* bih1     = (const float*)d_in[10];
    const float* bhh1     = (const float*)d_in[11];
    const float* fcw      = (const float*)d_in[12];
    const float* fcb      = (const float*)d_in[13];

    static bool init = false;
    if (!init) {
        cudaFuncSetAttribute(k_recur, cudaFuncAttributeMaxDynamicSharedMemorySize,
                             (int)SMEM_TOTAL);
        init = true;
    }

    k_reset<<<32, 256>>>();
    k_pre<<<(2 * G4 * 32 + 255) / 256, 256>>>(Wih0, cond, emb, bih0, bhh0, bih1, bhh1);
    k_recur<<<NB, 256, SMEM_TOTAL>>>(ids, Whh0, Wih1, Whh1);
    k_ce<<<TSTEPS * BB, 256>>>(ids, fcw, fcb);
    k_loss<<<1, 256>>>(mask, (float*)d_out);
}

// round 13
// speedup vs baseline: 1.3378x; 1.0907x over previous
#include <cuda_runtime.h>
#include <cuda_fp16.h>

// Problem constants
#define H      1024
#define BB     2
#define CLS    30
#define EMBD   128
#define SEQ    1024
#define TSTEPS 1023      // n_seq - 1
#define G4     4096      // 4*H gate rows per layer

// Block partition: gate rows of an element live in ONE block.
#define NBL0   43        // L0 blocks: 24 elements x 4 gate rows = 96 rows
#define EL0    24
#define NBL1   86        // L1 blocks: 12 elements x 8 rows (4 Wih1 + 4 Whh1) = 96
#define EL1    12
#define NB     (NBL0 + NBL1)   // 129 blocks, one per SM, co-resident
#define RPB    96
#define NT     384       // 12 warps: 6 tiles x (register-half warp + ldmatrix-half warp)
#define KSPLIT 28        // register-half covers k-steps [0,28); ldmatrix-half [28,64)

// SMEM layout: padded weight rows (conflict-free ldmatrix), h staging, 2 gate banks
#define RS     1032                    // halves per weight row (1024 + 8 pad)
#define RSB    (RS * 2)                // 2064 bytes
#define SWB    ((size_t)RPB * RSB)     // 198144 bytes of weights
#define HSB    (4 * RSB)               // 4 padded h rows (8256 bytes)
#define GRB    (RPB * 2 * sizeof(float))                   // one gres bank: 768B
#define SMEM_TOTAL (SWB + HSB + 2 * GRB)                   // 207936

// ---------------- persistent device state ----------------
__device__ float    d_condW0[BB * G4];                   // cond @ Wih0[:, :H]^T + b_ih0 + b_hh0
__device__ float    d_embproj[CLS * G4];                 // emb  @ Wih0[:, H:]^T per class
__device__ float    d_bias1[G4];                         // b_ih1 + b_hh1
// Tagged h exchange: word = {lo16: fp16 h, hi16: step tag (writer step + 1)}
__device__ __align__(16) unsigned d_h0t[2][BB * H];      // double-buffered tagged h0
__device__ __align__(16) unsigned d_h1t[2][BB * H];      // double-buffered tagged h1
__device__ float    d_h1hist[(size_t)TSTEPS * BB * H];   // layer-1 outputs (fp32) for CE
__device__ unsigned d_ctr[64];                           // staged-epoch ctrs: [0]=L0, [32]=L1
__device__ float    d_nll[TSTEPS * BB];

// ---------------- helpers ----------------
__device__ __forceinline__ float tanhap(float x) {
    float y; asm("tanh.approx.f32 %0, %1;" : "=f"(y) : "f"(x)); return y;
}
__device__ __forceinline__ float sigap(float x) { return 0.5f * tanhap(0.5f * x) + 0.5f; }

// Backpressure wait on STAGED epoch counters (published right after staging ->
// a full step of slack, normally pre-satisfied). Bounded spin: sync bug
// degrades to a wrong answer + diagnostics, never a hang.
__device__ __forceinline__ void waitc(int t0, int t1, int tid) {
    if (tid == 0 && t0 > 0) {
        const unsigned* p = &d_ctr[0];
        unsigned v; unsigned spins = 0;
        do {
            asm volatile("ld.acquire.gpu.u32 %0, [%1];" : "=r"(v) : "l"(p) : "memory");
        } while ((int)v < t0 && ++spins < (1u << 16));
    } else if (tid == 32 && t1 > 0) {
        const unsigned* p = &d_ctr[32];
        unsigned v; unsigned spins = 0;
        do {
            asm volatile("ld.acquire.gpu.u32 %0, [%1];" : "=r"(v) : "l"(p) : "memory");
        } while ((int)v < t1 && ++spins < (1u << 16));
    }
    __syncthreads();
}

// Tagged uint4 load with retry-until-fresh (detection fused with the data load).
__device__ __forceinline__ uint4 ld_tagged(const unsigned* src, unsigned exp) {
    uint4 w; unsigned spins = 0; bool okf;
    do {
        asm volatile("ld.relaxed.gpu.global.v4.u32 {%0,%1,%2,%3}, [%4];"
                     : "=r"(w.x), "=r"(w.y), "=r"(w.z), "=r"(w.w) : "l"(src));
        okf = ((w.x >> 16) == exp) & ((w.y >> 16) == exp)
            & ((w.z >> 16) == exp) & ((w.w >> 16) == exp);
    } while (!okf && ++spins < (1u << 16));
    return w;
}

// ---------------- prep kernels ----------------
__global__ void k_reset() {
    int i = blockIdx.x * blockDim.x + threadIdx.x;
    if (i < 64) d_ctr[i] = 0u;
    if (i < 2 * BB * H) {                 // tag 0 == "step -1", h = +0
        ((unsigned*)d_h0t)[i] = 0u;
        ((unsigned*)d_h1t)[i] = 0u;
    }
}

// Coalesced prep: one warp per weight row, shfl reduction.
__global__ void k_pre(const float* __restrict__ Wih0, const float* __restrict__ cond,
                      const float* __restrict__ emb,
                      const float* __restrict__ bih0, const float* __restrict__ bhh0,
                      const float* __restrict__ bih1, const float* __restrict__ bhh1) {
    int wg = (blockIdx.x * blockDim.x + threadIdx.x) >> 5;
    int lane = threadIdx.x & 31;
    if (wg < G4) {
        int j = wg;
        const float* wr = Wih0 + (size_t)j * 1152;
        float s0 = 0.f, s1 = 0.f;
#pragma unroll 8
        for (int i = 0; i < 32; ++i) {
            float w = wr[i * 32 + lane];
            s0 += w * cond[i * 32 + lane];
            s1 += w * cond[H + i * 32 + lane];
        }
#pragma unroll
        for (int off = 16; off > 0; off >>= 1) {
            s0 += __shfl_xor_sync(0xffffffffu, s0, off);
            s1 += __shfl_xor_sync(0xffffffffu, s1, off);
        }
        if (lane == 0) {
            float b = bih0[j] + bhh0[j];
            d_condW0[j]      = s0 + b;
            d_condW0[G4 + j] = s1 + b;
            d_bias1[j] = bih1[j] + bhh1[j];
        }
    } else if (wg < 2 * G4) {
        int j = wg - G4;
        const float* wr = Wih0 + (size_t)j * 1152 + H;
        float w0 = wr[lane], w1 = wr[32 + lane], w2 = wr[64 + lane], w3 = wr[96 + lane];
        for (int c = 0; c < CLS; ++c) {
            const float* eb = emb + c * EMBD;
            float s = w0 * eb[lane] + w1 * eb[32 + lane]
                    + w2 * eb[64 + lane] + w3 * eb[96 + lane];
#pragma unroll
            for (int off = 16; off > 0; off >>= 1)
                s += __shfl_xor_sync(0xffffffffu, s, off);
            if (lane == 0) d_embproj[c * G4 + j] = s;
        }
    }
}

// ---------------- persistent recurrent kernel (R12 + K-split dot) ----------------
// L0 block bk<NBL0: elements e = bk*24+j; weight slot s = j*4+g -> Whh0[g*1024+e]
// L1 block: elements e = lb*12+j; slots [0,48): Wih1 (input h0[s]),
//                                 slots [48,96): Whh1 (input h1[s-1])
// Dot: D[96x2] = W * h. 6 row-tiles of m16; tile t is computed by TWO warps:
//   warp 2t   (register-half): k-steps [0,KSPLIT), A preloaded in registers
//   warp 2t+1 (ldmatrix-half): k-steps [KSPLIT,64), A via ldmatrix
// Partials land in gresA / gresB; elementwise sums both banks.
// Availability: tag-in-payload. Backpressure: staged counters (1-step slack).
__global__ void __launch_bounds__(NT, 1)
k_recur(const long long* __restrict__ ids,
        const float* __restrict__ Whh0,
        const float* __restrict__ Wih1,
        const float* __restrict__ Whh1) {
    extern __shared__ char smem[];
    __half* sw  = (__half*)smem;
    __half* hsm = (__half*)(smem + SWB);
    float (*gresA)[2] = (float(*)[2])(smem + SWB + HSB);
    float (*gresB)[2] = (float(*)[2])(smem + SWB + HSB + GRB);
    const unsigned smem_u32 = (unsigned)__cvta_generic_to_shared(smem);
    const unsigned hsm_u32  = smem_u32 + (unsigned)SWB;

    const int tid = threadIdx.x, bk = blockIdx.x;
    const int lane = tid & 31, warp = tid >> 5;
    const int tile = warp >> 1, half = warp & 1;   // 6 tiles x 2 halves
    const bool isL1 = (bk >= NBL0);
    const int lb = isL1 ? (bk - NBL0) : bk;
    const int ebase = isL1 ? lb * EL1 : lb * EL0;

    // ---- prologue: gather fp32 weight rows -> fp16 SMEM, padded stride (once) ----
    for (int i = tid; i < RPB * 256; i += NT) {
        int s = i >> 8, c = i & 255;
        int g, e; const float* src;
        if (!isL1)      { g = s & 3;        e = ebase + (s >> 2);        src = Whh0; }
        else if (s < 48){ g = s & 3;        e = ebase + (s >> 2);        src = Wih1; }
        else            { int s2 = s - 48; g = s2 & 3; e = ebase + (s2 >> 2); src = Whh1; }
        __half2 out0, out1;
        if (e < H) {
            float4 v = *(const float4*)(src + (size_t)(g * 1024 + e) * H + c * 4);
            out0 = __floats2half2_rn(v.x, v.y);
            out1 = __floats2half2_rn(v.z, v.w);
        } else {
            out0 = __floats2half2_rn(0.f, 0.f); out1 = out0;
        }
        uint2 packed;
        packed.x = *reinterpret_cast<unsigned*>(&out0);
        packed.y = *reinterpret_cast<unsigned*>(&out1);
        *(uint2*)(sw + (size_t)s * RS + c * 4) = packed;
    }

    // ---- elementwise task setup (thread tid -> (j = tid/2, batch = tid&1)) ----
    const int nel = isL1 ? EL1 : EL0;
    const int jt = tid >> 1, bt = tid & 1;
    const int et = ebase + jt;
    const bool task = (jt < nel) && (et < H);
    float cw0 = 0, cw1 = 0, cw2 = 0, cw3 = 0;
    if (task) {
        if (!isL1) {
            const float* cw = d_condW0 + bt * G4 + et;
            cw0 = cw[0]; cw1 = cw[1024]; cw2 = cw[2048]; cw3 = cw[3072];
        } else {
            cw0 = d_bias1[et];        cw1 = d_bias1[et + 1024];
            cw2 = d_bias1[et + 2048]; cw3 = d_bias1[et + 3072];
        }
    }
    float cst = 0.f;   // cell state, register-resident for the whole sequence

    // ---- mma operand addressing (constant across steps) ----
    const int arow = lane & 15;
    const unsigned a_addr0 = smem_u32 + (unsigned)((tile * 16 + arow) * RSB + ((lane >> 4) * 16));
    const int nidx = lane >> 2;
    const bool nreal = (nidx < 2);
    const int hrowbase = (isL1 && tile >= 3) ? 2 : 0;   // L1 tiles 3-5 read h1p rows
    const unsigned b_addr0 = hsm_u32 + (unsigned)((hrowbase + (nreal ? nidx : 0)) * RSB
                                                  + (lane & 3) * 4);
    __syncthreads();   // SMEM weights ready

    // ---- register-half warps: preload step-invariant A for k-steps [0,KSPLIT) ----
    unsigned ar0[KSPLIT], ar1[KSPLIT], ar2[KSPLIT], ar3[KSPLIT];
    if (half == 0) {
#pragma unroll
        for (int k = 0; k < KSPLIT; ++k) {
            asm volatile("ldmatrix.sync.aligned.m8n8.x4.shared.b16 {%0,%1,%2,%3}, [%4];"
                         : "=r"(ar0[k]), "=r"(ar1[k]), "=r"(ar2[k]), "=r"(ar3[k])
                         : "r"(a_addr0 + k * 32));
        }
    }

    for (int s = 0; s < TSTEPS; ++s) {
        const int sb = s & 1, pb = (s + 1) & 1;
        const unsigned tagP = (unsigned)s;        // h{0,1}[s-1] tag
        const unsigned tagC = (unsigned)(s + 1);  // h0[s] tag (written this step)

        // per-step elementwise prefetch (token projection, L0 only) — before waits
        float ep0 = 0, ep1 = 0, ep2 = 0, ep3 = 0;
        if (task && !isL1) {
            int tok = (int)ids[bt * SEQ + s];
            const float* ep = d_embproj + tok * G4 + et;
            ep0 = ep[0]; ep1 = ep[1024]; ep2 = ep[2048]; ep3 = ep[3072];
        }

        // backpressure waits (staged counters; 1-step slack, rarely binding)
        if (!isL1) waitc(NBL0 * s, NBL1 * (s - 1), tid);
        else       waitc(0,        NBL1 * s,       tid);

        // stage h: tagged loads (availability detection fused with the load)
        if (!isL1) {                                   // rows 0-1 <- h0[s-1]
            for (int i = tid; i < 512; i += NT) {
                uint4 w = ld_tagged(d_h0t[pb] + i * 4, tagP);
                int word = i * 4, row = word >> 10, col = word & 1023;
                uint2 p;
                p.x = (w.x & 0xFFFFu) | (w.y << 16);
                p.y = (w.z & 0xFFFFu) | (w.w << 16);
                *(uint2*)(hsm + row * RS + col) = p;
            }
        } else {                                       // rows 0-1 <- h0[s]; 2-3 <- h1[s-1]
            for (int i = tid; i < 1024; i += NT) {
                const bool second = (i >= 512);
                const int j = second ? (i - 512) : i;
                const unsigned* src = (second ? d_h1t[pb] : d_h0t[sb]) + j * 4;
                uint4 w = ld_tagged(src, second ? tagP : tagC);
                int word = j * 4, row = (word >> 10) + (second ? 2 : 0), col = word & 1023;
                uint2 p;
                p.x = (w.x & 0xFFFFu) | (w.y << 16);
                p.y = (w.z & 0xFFFFu) | (w.w << 16);
                *(uint2*)(hsm + row * RS + col) = p;
            }
        }
        __syncthreads();   // hsm ready

        // publish staged-epoch (backpressure release for writers) — fire and forget
        if (tid == 0) {
            const unsigned* ctr = isL1 ? &d_ctr[32] : &d_ctr[0];
            asm volatile("red.release.gpu.global.add.u32 [%0], %1;"
                         :: "l"(ctr), "r"(1u) : "memory");
        }

        // ---- dot phase: each half-warp computes its K range, 4 acc chains ----
        {
            float d0[4] = {0,0,0,0}, d1[4] = {0,0,0,0};
            float d2[4] = {0,0,0,0}, d3[4] = {0,0,0,0};
            if (half == 0) {
                // register-half: k-steps [0,KSPLIT), A resident
#pragma unroll
                for (int k = 0; k < KSPLIT; ++k) {
                    unsigned b0 = 0, b1 = 0;
                    if (nreal) {
                        asm volatile("ld.shared.u32 %0, [%1];" : "=r"(b0) : "r"(b_addr0 + k * 32));
                        asm volatile("ld.shared.u32 %0, [%1];" : "=r"(b1) : "r"(b_addr0 + k * 32 + 16));
                    }
                    const int ch = k & 3;
                    asm volatile("mma.sync.aligned.m16n8k16.row.col.f32.f16.f16.f32 "
                                 "{%0,%1,%2,%3}, {%4,%5,%6,%7}, {%8,%9}, {%0,%1,%2,%3};"
                                 : "+f"(d0[ch]), "+f"(d1[ch]), "+f"(d2[ch]), "+f"(d3[ch])
                                 : "r"(ar0[k]), "r"(ar1[k]), "r"(ar2[k]), "r"(ar3[k]),
                                   "r"(b0), "r"(b1));
                }
            } else {
                // ldmatrix-half: k-steps [KSPLIT,64)
#pragma unroll
                for (int k = KSPLIT; k < 64; ++k) {
                    unsigned a0, a1, a2, a3;
                    asm volatile("ldmatrix.sync.aligned.m8n8.x4.shared.b16 {%0,%1,%2,%3}, [%4];"
                                 : "=r"(a0), "=r"(a1), "=r"(a2), "=r"(a3)
                                 : "r"(a_addr0 + k * 32));
                    unsigned b0 = 0, b1 = 0;
                    if (nreal) {
                        asm volatile("ld.shared.u32 %0, [%1];" : "=r"(b0) : "r"(b_addr0 + k * 32));
                        asm volatile("ld.shared.u32 %0, [%1];" : "=r"(b1) : "r"(b_addr0 + k * 32 + 16));
                    }
                    const int ch = k & 3;
                    asm volatile("mma.sync.aligned.m16n8k16.row.col.f32.f16.f16.f32 "
                                 "{%0,%1,%2,%3}, {%4,%5,%6,%7}, {%8,%9}, {%0,%1,%2,%3};"
                                 : "+f"(d0[ch]), "+f"(d1[ch]), "+f"(d2[ch]), "+f"(d3[ch])
                                 : "r"(a0), "r"(a1), "r"(a2), "r"(a3), "r"(b0), "r"(b1));
                }
            }
            if ((lane & 3) == 0) {
                const int g = lane >> 2;
                const int r = tile * 16 + g;
                float2 lo = make_float2(d0[0] + d0[1] + d0[2] + d0[3],
                                        d1[0] + d1[1] + d1[2] + d1[3]);
                float2 hi = make_float2(d2[0] + d2[1] + d2[2] + d2[3],
                                        d3[0] + d3[1] + d3[2] + d3[3]);
                if (half == 0) {
                    *(float2*)&gresA[r][0]     = lo;
                    *(float2*)&gresA[r + 8][0] = hi;
                } else {
                    *(float2*)&gresB[r][0]     = lo;
                    *(float2*)&gresB[r + 8][0] = hi;
                }
            }
        }
        __syncthreads();   // both gres banks visible block-wide

        // ---- elementwise phase (sum both banks, tagged h publish) ----
        if (task) {
            const int j4 = jt * 4;
            float gi, gf, gg, go;
            if (!isL1) {
                gi = gresA[j4 + 0][bt] + gresB[j4 + 0][bt] + cw0 + ep0;
                gf = gresA[j4 + 1][bt] + gresB[j4 + 1][bt] + cw1 + ep1;
                gg = gresA[j4 + 2][bt] + gresB[j4 + 2][bt] + cw2 + ep2;
                go = gresA[j4 + 3][bt] + gresB[j4 + 3][bt] + cw3 + ep3;
            } else {
                gi = gresA[j4 + 0][bt] + gresB[j4 + 0][bt]
                   + gresA[48 + j4 + 0][bt] + gresB[48 + j4 + 0][bt] + cw0;
                gf = gresA[j4 + 1][bt] + gresB[j4 + 1][bt]
                   + gresA[48 + j4 + 1][bt] + gresB[48 + j4 + 1][bt] + cw1;
                gg = gresA[j4 + 2][bt] + gresB[j4 + 2][bt]
                   + gresA[48 + j4 + 2][bt] + gresB[48 + j4 + 2][bt] + cw2;
                go = gresA[j4 + 3][bt] + gresB[j4 + 3][bt]
                   + gresA[48 + j4 + 3][bt] + gresB[48 + j4 + 3][bt] + cw3;
            }
            cst = sigap(gf) * cst + sigap(gi) * tanhap(gg);
            float h = sigap(go) * tanhap(cst);
            unsigned hw = (unsigned)__half_as_ushort(__float2half(h)) | (tagC << 16);
            if (!isL1) {
                asm volatile("st.relaxed.gpu.global.u32 [%0], %1;"
                             :: "l"(&d_h0t[sb][bt * H + et]), "r"(hw) : "memory");
            } else {
                asm volatile("st.relaxed.gpu.global.u32 [%0], %1;"
                             :: "l"(&d_h1t[sb][bt * H + et]), "r"(hw) : "memory");
                d_h1hist[(size_t)s * (BB * H) + bt * H + et] = h;
            }
        }
        // no end-of-step sync: availability is via tags; the next iteration's
        // waitc __syncthreads isolates hsm/gres reuse.
    }
}

// ---------------- CE kernels ----------------
// Block handles 14 tokens; fcw staged once per block into dynamic SMEM.
#define CE_TPB   256
#define CE_TOK   14
#define CE_SMEM  (CLS * H * sizeof(float))
__global__ void k_ce(const long long* __restrict__ ids,
                     const float* __restrict__ fcw, const float* __restrict__ fcb) {
    extern __shared__ float sfw[];          // [CLS][H]
    __shared__ float slg[8][32];
    const int tid = threadIdx.x, lane = tid & 31, warp = tid >> 5;

    for (int i = tid; i < (CLS * H) / 4; i += CE_TPB)
        *(float4*)(sfw + i * 4) = *(const float4*)(fcw + i * 4);
    __syncthreads();

    for (int pass = 0; pass < 2; ++pass) {
        int lt = warp + pass * 8;
        int m = blockIdx.x * CE_TOK + lt;
        if (lt < CE_TOK && m < TSTEPS * BB) {
            const int b = m & 1, t = m >> 1;
            // load h slice: lane holds h[i*32+lane], i<32
            float hreg[32];
            const float* hp = d_h1hist + (size_t)t * BB * H + b * H;
#pragma unroll
            for (int i = 0; i < 32; ++i) hreg[i] = hp[i * 32 + lane];
            for (int c = 0; c < CLS; ++c) {
                const float* wr = sfw + c * H;
                float s = 0.f;
#pragma unroll
                for (int i = 0; i < 32; ++i) s += wr[i * 32 + lane] * hreg[i];
#pragma unroll
                for (int off = 16; off > 0; off >>= 1)
                    s += __shfl_xor_sync(0xffffffffu, s, off);
                if (lane == 0) slg[warp][c] = s + fcb[c];
            }
            __syncwarp();
            if (lane == 0) {
                float mx = -1e30f;
                for (int c = 0; c < CLS; ++c) mx = fmaxf(mx, slg[warp][c]);
                float se = 0.f;
                for (int c = 0; c < CLS; ++c) se += expf(slg[warp][c] - mx);
                float lse = mx + logf(se);
                int tgt = (int)ids[b * SEQ + t + 1];
                d_nll[m] = lse - slg[warp][tgt];
            }
            __syncwarp();
        }
    }
}

__global__ void k_loss(const float* __restrict__ mask, float* __restrict__ out) {
    __shared__ float s1s[256], s2s[256];
    const int tid = threadIdx.x;
    float sn = 0.f, sm = 0.f;
    for (int i = tid; i < TSTEPS * BB; i += 256) sn += d_nll[i];
    for (int i = tid; i < BB * TSTEPS; i += 256) {
        int b = i / TSTEPS, t = i % TSTEPS;
        sm += mask[b * SEQ + t + 1];
    }
    s1s[tid] = sn; s2s[tid] = sm;
    __syncthreads();
    for (int o = 128; o > 0; o >>= 1) {
        if (tid < o) { s1s[tid] += s1s[tid + o]; s2s[tid] += s2s[tid + o]; }
        __syncthreads();
    }
    if (tid == 0) {
        float ce = s1s[0] / (float)(TSTEPS * BB);
        float masked = ce * s2s[0] / s2s[0];   // matches reference (incl. mask==0 -> NaN)
        out[0] = ce + masked;
    }
}

// ---------------- launch ----------------
extern "C" void kernel_launch(void* const* d_in, const int* in_sizes, int n_in,
                              void* d_out, int out_size) {
    const long long* ids  = (const long long*)d_in[0];
    const float* mask     = (const float*)d_in[1];
    const float* cond     = (const float*)d_in[2];
    const float* emb      = (const float*)d_in[3];
    const float* Wih0     = (const float*)d_in[4];
    const float* Whh0     = (const float*)d_in[5];
    const float* bih0     = (const float*)d_in[6];
    const float* bhh0     = (const float*)d_in[7];
    const float* Wih1     = (const float*)d_in[8];
    const float* Whh1     = (const float*)d_in[9];
    const float* bih1     = (const float*)d_in[10];
    const float* bhh1     = (const float*)d_in[11];
    const float* fcw      = (const float*)d_in[12];
    const float* fcb      = (const float*)d_in[13];

    static bool init = false;
    if (!init) {
        cudaFuncSetAttribute(k_recur, cudaFuncAttributeMaxDynamicSharedMemorySize,
                             (int)SMEM_TOTAL);
        cudaFuncSetAttribute(k_ce, cudaFuncAttributeMaxDynamicSharedMemorySize,
                             (int)CE_SMEM);
        init = true;
    }

    k_reset<<<32, 256>>>();
    k_pre<<<(2 * G4 * 32 + 255) / 256, 256>>>(Wih0, cond, emb, bih0, bhh0, bih1, bhh1);
    k_recur<<<NB, NT, SMEM_TOTAL>>>(ids, Whh0, Wih1, Whh1);
    k_ce<<<(TSTEPS * BB + CE_TOK - 1) / CE_TOK, CE_TPB, CE_SMEM>>>(ids, fcw, fcb);
    k_loss<<<1, 256>>>(mask, (float*)d_out);
}

// round 15
// speedup vs baseline: 1.5107x; 1.1292x over previous
#include <cuda_runtime.h>
#include <cuda_fp16.h>

// Problem constants
#define H      1024
#define BB     2
#define CLS    30
#define EMBD   128
#define SEQ    1024
#define TSTEPS 1023      // n_seq - 1
#define G4     4096      // 4*H gate rows per layer

// Block partition: gate rows of an element live in ONE block.
#define NBL0   43        // L0 blocks: 24 elements x 4 gate rows = 96 rows
#define EL0    24
#define NBL1   86        // L1 blocks: 12 elements x 8 rows (4 Wih1 + 4 Whh1) = 96
#define EL1    12
#define NB     (NBL0 + NBL1)   // 129 blocks, one per SM, co-resident
#define RPB    96
#define NT     384       // 12 warps: 6 tiles x 2 half-warps
#define PRE    20        // k-steps preloaded per half-warp (80 regs)

// SMEM layout: padded weight rows (conflict-free ldmatrix), permuted B, 2 gate banks
#define RS     1032                    // halves per weight row (1024 + 8 pad)
#define RSB    (RS * 2)                // 2064 bytes
#define SWB    ((size_t)RPB * RSB)     // 198144 bytes of weights
#define BPR    2112                    // permuted-B row stride (bank-disjoint rows)
#define BPB    (4 * BPR)               // 8448 bytes (4 h rows)
#define GRB    (RPB * 2 * sizeof(float))
#define SMEM_TOTAL (SWB + BPB + 2 * GRB)   // 208128

// ---------------- persistent device state ----------------
__device__ float    d_condW0[BB * G4];
__device__ float    d_embproj[CLS * G4];
__device__ float    d_bias1[G4];
// Tagged h exchange: word = {lo16: fp16 h, hi16: step tag (writer step + 1)}
__device__ __align__(16) unsigned d_h0t[2][BB * H];
__device__ __align__(16) unsigned d_h1t[2][BB * H];
__device__ __half   d_h1h[(size_t)TSTEPS * BB * H];      // fp16 layer-1 outputs for CE
__device__ unsigned d_ctr[64];                           // staged-epoch ctrs: [0]=L0, [32]=L1
__device__ float    d_nll[TSTEPS * BB];

// ---------------- helpers ----------------
__device__ __forceinline__ float tanhap(float x) {
    float y; asm("tanh.approx.f32 %0, %1;" : "=f"(y) : "f"(x)); return y;
}
__device__ __forceinline__ float sigap(float x) { return 0.5f * tanhap(0.5f * x) + 0.5f; }

// Backpressure wait on STAGED epoch counters (published right after staging ->
// a full step of slack, normally pre-satisfied). Bounded spin: sync bug
// degrades to a wrong answer + diagnostics, never a container-killing hang.
__device__ __forceinline__ void waitc(int t0, int t1, int tid) {
    if (tid == 0 && t0 > 0) {
        const unsigned* p = &d_ctr[0];
        unsigned v; unsigned spins = 0;
        do {
            asm volatile("ld.acquire.gpu.u32 %0, [%1];" : "=r"(v) : "l"(p) : "memory");
        } while ((int)v < t0 && ++spins < (1u << 16));
    } else if (tid == 32 && t1 > 0) {
        const unsigned* p = &d_ctr[32];
        unsigned v; unsigned spins = 0;
        do {
            asm volatile("ld.acquire.gpu.u32 %0, [%1];" : "=r"(v) : "l"(p) : "memory");
        } while ((int)v < t1 && ++spins < (1u << 16));
    }
    __syncthreads();
}

__device__ __forceinline__ uint4 ld4g(const unsigned* p) {
    uint4 w;
    asm volatile("ld.relaxed.gpu.global.v4.u32 {%0,%1,%2,%3}, [%4];"
                 : "=r"(w.x), "=r"(w.y), "=r"(w.z), "=r"(w.w) : "l"(p));
    return w;
}
__device__ __forceinline__ bool tagok(uint4 w, unsigned exp) {
    return ((w.x >> 16) == exp) & ((w.y >> 16) == exp)
         & ((w.z >> 16) == exp) & ((w.w >> 16) == exp);
}

// Permuted-B write: word w (2 halves) of h row -> B-fragment order so that a
// k-step PAIR is one contiguous 16B chunk per (n,c) thread -> ld.shared.v4.
__device__ __forceinline__ void bpwrite(char* bp, int row, int w, unsigned val) {
    int k = w >> 3, c = w & 3, hf = (w >> 2) & 1;
    int p = k >> 1, e = k & 1;
    *(unsigned*)(bp + row * BPR + p * 64 + c * 16 + (2 * e + hf) * 4) = val;
}

// ---------------- prep kernels ----------------
__global__ void k_reset() {
    int i = blockIdx.x * blockDim.x + threadIdx.x;
    if (i < 64) d_ctr[i] = 0u;
    if (i < 2 * BB * H) {                 // tag 0 == "step -1", h = +0
        ((unsigned*)d_h0t)[i] = 0u;
        ((unsigned*)d_h1t)[i] = 0u;
    }
}

// Coalesced prep: one warp per weight row, shfl reduction.
__global__ void k_pre(const float* __restrict__ Wih0, const float* __restrict__ cond,
                      const float* __restrict__ emb,
                      const float* __restrict__ bih0, const float* __restrict__ bhh0,
                      const float* __restrict__ bih1, const float* __restrict__ bhh1) {
    int wg = (blockIdx.x * blockDim.x + threadIdx.x) >> 5;
    int lane = threadIdx.x & 31;
    if (wg < G4) {
        int j = wg;
        const float* wr = Wih0 + (size_t)j * 1152;
        float s0 = 0.f, s1 = 0.f;
#pragma unroll 8
        for (int i = 0; i < 32; ++i) {
            float w = wr[i * 32 + lane];
            s0 += w * cond[i * 32 + lane];
            s1 += w * cond[H + i * 32 + lane];
        }
#pragma unroll
        for (int off = 16; off > 0; off >>= 1) {
            s0 += __shfl_xor_sync(0xffffffffu, s0, off);
            s1 += __shfl_xor_sync(0xffffffffu, s1, off);
        }
        if (lane == 0) {
            float b = bih0[j] + bhh0[j];
            d_condW0[j]      = s0 + b;
            d_condW0[G4 + j] = s1 + b;
            d_bias1[j] = bih1[j] + bhh1[j];
        }
    } else if (wg < 2 * G4) {
        int j = wg - G4;
        const float* wr = Wih0 + (size_t)j * 1152 + H;
        float w0 = wr[lane], w1 = wr[32 + lane], w2 = wr[64 + lane], w3 = wr[96 + lane];
        for (int c = 0; c < CLS; ++c) {
            const float* eb = emb + c * EMBD;
            float s = w0 * eb[lane] + w1 * eb[32 + lane]
                    + w2 * eb[64 + lane] + w3 * eb[96 + lane];
#pragma unroll
            for (int off = 16; off > 0; off >>= 1)
                s += __shfl_xor_sync(0xffffffffu, s, off);
            if (lane == 0) d_embproj[c * G4 + j] = s;
        }
    }
}

// ---------------- persistent recurrent kernel ----------------
// Dot: D[96x2] = W * h; tile t (16 rows) split across 2 warps by K:
//   half0: preload k[0,20) + ldmatrix k[40,52)
//   half1: preload k[20,40) + ldmatrix k[52,64)
// B loaded as one ld.shared.v4 per k-step PAIR from the permuted staging layout.
// Availability: tag-in-payload (parallel-poll). Backpressure: staged counters.
__global__ void __launch_bounds__(NT, 1)
k_recur(const long long* __restrict__ ids,
        const float* __restrict__ Whh0,
        const float* __restrict__ Wih1,
        const float* __restrict__ Whh1) {
    extern __shared__ char smem[];
    __half* sw  = (__half*)smem;
    char*   bp  = smem + SWB;
    float (*gresA)[2] = (float(*)[2])(smem + SWB + BPB);
    float (*gresB)[2] = (float(*)[2])(smem + SWB + BPB + GRB);
    const unsigned smem_u32 = (unsigned)__cvta_generic_to_shared(smem);
    const unsigned bp_u32   = smem_u32 + (unsigned)SWB;

    const int tid = threadIdx.x, bk = blockIdx.x;
    const int lane = tid & 31, warp = tid >> 5;
    const int tile = warp >> 1, half = warp & 1;
    const bool isL1 = (bk >= NBL0);
    const int lb = isL1 ? (bk - NBL0) : bk;
    const int ebase = isL1 ? lb * EL1 : lb * EL0;

    // ---- prologue: gather fp32 weight rows -> fp16 SMEM, padded stride (once) ----
    for (int i = tid; i < RPB * 256; i += NT) {
        int s = i >> 8, c = i & 255;
        int g, e; const float* src;
        if (!isL1)      { g = s & 3;        e = ebase + (s >> 2);        src = Whh0; }
        else if (s < 48){ g = s & 3;        e = ebase + (s >> 2);        src = Wih1; }
        else            { int s2 = s - 48; g = s2 & 3; e = ebase + (s2 >> 2); src = Whh1; }
        __half2 out0, out1;
        if (e < H) {
            float4 v = *(const float4*)(src + (size_t)(g * 1024 + e) * H + c * 4);
            out0 = __floats2half2_rn(v.x, v.y);
            out1 = __floats2half2_rn(v.z, v.w);
        } else {
            out0 = __floats2half2_rn(0.f, 0.f); out1 = out0;
        }
        uint2 packed;
        packed.x = *reinterpret_cast<unsigned*>(&out0);
        packed.y = *reinterpret_cast<unsigned*>(&out1);
        *(uint2*)(sw + (size_t)s * RS + c * 4) = packed;
    }

    // ---- elementwise task setup ----
    const int nel = isL1 ? EL1 : EL0;
    const int jt = tid >> 1, bt = tid & 1;
    const int et = ebase + jt;
    const bool task = (jt < nel) && (et < H);
    float cw0 = 0, cw1 = 0, cw2 = 0, cw3 = 0;
    if (task) {
        if (!isL1) {
            const float* cw = d_condW0 + bt * G4 + et;
            cw0 = cw[0]; cw1 = cw[1024]; cw2 = cw[2048]; cw3 = cw[3072];
        } else {
            cw0 = d_bias1[et];        cw1 = d_bias1[et + 1024];
            cw2 = d_bias1[et + 2048]; cw3 = d_bias1[et + 3072];
        }
    }
    float cst = 0.f;

    // ---- mma operand addressing ----
    const int arow = lane & 15;
    const unsigned a_addr0 = smem_u32 + (unsigned)((tile * 16 + arow) * RSB + ((lane >> 4) * 16));
    const int nidx = lane >> 2;
    const bool nreal = (nidx < 2);
    const int hrowbase = (isL1 && tile >= 3) ? 2 : 0;
    const unsigned b_base = bp_u32 + (unsigned)((hrowbase + (nreal ? nidx : 0)) * BPR
                                                + (lane & 3) * 16);
    const int PS = half ? PRE : 0;       // preload k-start
    const int LS = half ? 52 : 40;       // ldmatrix k-start (6 pairs each)
    __syncthreads();   // SMEM weights ready

    // ---- preload step-invariant A fragments (both halves, PRE k-steps each) ----
    unsigned ar0[PRE], ar1[PRE], ar2[PRE], ar3[PRE];
#pragma unroll
    for (int j = 0; j < PRE; ++j) {
        asm volatile("ldmatrix.sync.aligned.m8n8.x4.shared.b16 {%0,%1,%2,%3}, [%4];"
                     : "=r"(ar0[j]), "=r"(ar1[j]), "=r"(ar2[j]), "=r"(ar3[j])
                     : "r"(a_addr0 + (PS + j) * 32));
    }

    for (int s = 0; s < TSTEPS; ++s) {
        const int sb = s & 1, pb = (s + 1) & 1;
        const unsigned tagP = (unsigned)s;
        const unsigned tagC = (unsigned)(s + 1);

        // per-step elementwise prefetch (token projection, L0 only)
        float ep0 = 0, ep1 = 0, ep2 = 0, ep3 = 0;
        if (task && !isL1) {
            int tok = (int)ids[bt * SEQ + s];
            const float* ep = d_embproj + tok * G4 + et;
            ep0 = ep[0]; ep1 = ep[1024]; ep2 = ep[2048]; ep3 = ep[3072];
        }

        // backpressure waits (staged counters; 1-step slack, rarely binding)
        if (!isL1) waitc(NBL0 * s, NBL1 * (s - 1), tid);
        else       waitc(0,        NBL1 * s,       tid);

        // ---- stage h: parallel-poll tagged loads -> permuted B layout ----
        if (!isL1) {                       // 512 uint4 of h0[s-1]
            const unsigned* q = d_h0t[pb];
            const int i1 = tid + NT;
            uint4 w0v, w1v;
            bool ok0 = false, ok1 = (i1 >= 512);
            unsigned spins = 0;
            do {
                if (!ok0) { w0v = ld4g(q + (size_t)tid * 4); ok0 = tagok(w0v, tagP); }
                if (!ok1) { w1v = ld4g(q + (size_t)i1 * 4);  ok1 = tagok(w1v, tagP); }
            } while ((!ok0 || !ok1) && ++spins < (1u << 16));
            {
                int row = tid >> 8, w = (tid & 255) * 2;
                bpwrite(bp, row, w,     (w0v.x & 0xFFFFu) | (w0v.y << 16));
                bpwrite(bp, row, w + 1, (w0v.z & 0xFFFFu) | (w0v.w << 16));
            }
            if (i1 < 512) {
                int row = i1 >> 8, w = (i1 & 255) * 2;
                bpwrite(bp, row, w,     (w1v.x & 0xFFFFu) | (w1v.y << 16));
                bpwrite(bp, row, w + 1, (w1v.z & 0xFFFFu) | (w1v.w << 16));
            }
        } else {                           // 1024 uint4: h0[s] (rows 0-1), h1[s-1] (2-3)
            const int i0 = tid, i1 = tid + NT, i2 = tid + 2 * NT;
            const unsigned* q0 = d_h0t[sb] + (size_t)i0 * 4;
            const unsigned* q1 = (i1 < 512) ? (d_h0t[sb] + (size_t)i1 * 4)
                                            : (d_h1t[pb] + (size_t)(i1 - 512) * 4);
            const unsigned* q2 = d_h1t[pb] + (size_t)(i2 - 512) * 4;
            const unsigned e0 = tagC, e1 = (i1 < 512) ? tagC : tagP, e2 = tagP;
            uint4 w0v, w1v, w2v;
            bool ok0 = false, ok1 = false, ok2 = (i2 >= 1024);
            unsigned spins = 0;
            do {
                if (!ok0) { w0v = ld4g(q0); ok0 = tagok(w0v, e0); }
                if (!ok1) { w1v = ld4g(q1); ok1 = tagok(w1v, e1); }
                if (!ok2) { w2v = ld4g(q2); ok2 = tagok(w2v, e2); }
            } while ((!ok0 || !ok1 || !ok2) && ++spins < (1u << 16));
            {
                int j = i0, row = j >> 8, w = (j & 255) * 2;
                bpwrite(bp, row, w,     (w0v.x & 0xFFFFu) | (w0v.y << 16));
                bpwrite(bp, row, w + 1, (w0v.z & 0xFFFFu) | (w0v.w << 16));
            }
            {
                int j = (i1 < 512) ? i1 : (i1 - 512);
                int row = (j >> 8) + ((i1 < 512) ? 0 : 2), w = (j & 255) * 2;
                bpwrite(bp, row, w,     (w1v.x & 0xFFFFu) | (w1v.y << 16));
                bpwrite(bp, row, w + 1, (w1v.z & 0xFFFFu) | (w1v.w << 16));
            }
            if (i2 < 1024) {
                int j = i2 - 512, row = (j >> 8) + 2, w = (j & 255) * 2;
                bpwrite(bp, row, w,     (w2v.x & 0xFFFFu) | (w2v.y << 16));
                bpwrite(bp, row, w + 1, (w2v.z & 0xFFFFu) | (w2v.w << 16));
            }
        }
        __syncthreads();   // permuted B ready

        // publish staged-epoch (backpressure release) — fire and forget
        if (tid == 0) {
            const unsigned* ctr = isL1 ? &d_ctr[32] : &d_ctr[0];
            asm volatile("red.release.gpu.global.add.u32 [%0], %1;"
                         :: "l"(ctr), "r"(1u) : "memory");
        }

        // ---- dot phase ----
        {
            float d0[4] = {0,0,0,0}, d1[4] = {0,0,0,0};
            float d2[4] = {0,0,0,0}, d3[4] = {0,0,0,0};
            // preload region: PRE k-steps (10 pairs), A resident
#pragma unroll
            for (int jp = 0; jp < PRE / 2; ++jp) {
                uint4 b = make_uint4(0, 0, 0, 0);
                if (nreal) {
                    asm volatile("ld.shared.v4.u32 {%0,%1,%2,%3}, [%4];"
                                 : "=r"(b.x), "=r"(b.y), "=r"(b.z), "=r"(b.w)
                                 : "r"(b_base + (PS / 2 + jp) * 64));
                }
                const int c0 = (jp & 1) * 2, c1 = c0 + 1;
                asm volatile("mma.sync.aligned.m16n8k16.row.col.f32.f16.f16.f32 "
                             "{%0,%1,%2,%3}, {%4,%5,%6,%7}, {%8,%9}, {%0,%1,%2,%3};"
                             : "+f"(d0[c0]), "+f"(d1[c0]), "+f"(d2[c0]), "+f"(d3[c0])
                             : "r"(ar0[2*jp]), "r"(ar1[2*jp]), "r"(ar2[2*jp]), "r"(ar3[2*jp]),
                               "r"(b.x), "r"(b.y));
                asm volatile("mma.sync.aligned.m16n8k16.row.col.f32.f16.f16.f32 "
                             "{%0,%1,%2,%3}, {%4,%5,%6,%7}, {%8,%9}, {%0,%1,%2,%3};"
                             : "+f"(d0[c1]), "+f"(d1[c1]), "+f"(d2[c1]), "+f"(d3[c1])
                             : "r"(ar0[2*jp+1]), "r"(ar1[2*jp+1]), "r"(ar2[2*jp+1]), "r"(ar3[2*jp+1]),
                               "r"(b.z), "r"(b.w));
            }
            // ldmatrix region: 12 k-steps (6 pairs)
#pragma unroll
            for (int jp = 0; jp < 6; ++jp) {
                unsigned a0, a1, a2, a3, a4, a5, a6, a7;
                asm volatile("ldmatrix.sync.aligned.m8n8.x4.shared.b16 {%0,%1,%2,%3}, [%4];"
                             : "=r"(a0), "=r"(a1), "=r"(a2), "=r"(a3)
                             : "r"(a_addr0 + (LS + 2 * jp) * 32));
                asm volatile("ldmatrix.sync.aligned.m8n8.x4.shared.b16 {%0,%1,%2,%3}, [%4];"
                             : "=r"(a4), "=r"(a5), "=r"(a6), "=r"(a7)
                             : "r"(a_addr0 + (LS + 2 * jp + 1) * 32));
                uint4 b = make_uint4(0, 0, 0, 0);
                if (nreal) {
                    asm volatile("ld.shared.v4.u32 {%0,%1,%2,%3}, [%4];"
                                 : "=r"(b.x), "=r"(b.y), "=r"(b.z), "=r"(b.w)
                                 : "r"(b_base + (LS / 2 + jp) * 64));
                }
                const int c0 = (jp & 1) * 2, c1 = c0 + 1;
                asm volatile("mma.sync.aligned.m16n8k16.row.col.f32.f16.f16.f32 "
                             "{%0,%1,%2,%3}, {%4,%5,%6,%7}, {%8,%9}, {%0,%1,%2,%3};"
                             : "+f"(d0[c0]), "+f"(d1[c0]), "+f"(d2[c0]), "+f"(d3[c0])
                             : "r"(a0), "r"(a1), "r"(a2), "r"(a3), "r"(b.x), "r"(b.y));
                asm volatile("mma.sync.aligned.m16n8k16.row.col.f32.f16.f16.f32 "
                             "{%0,%1,%2,%3}, {%4,%5,%6,%7}, {%8,%9}, {%0,%1,%2,%3};"
                             : "+f"(d0[c1]), "+f"(d1[c1]), "+f"(d2[c1]), "+f"(d3[c1])
                             : "r"(a4), "r"(a5), "r"(a6), "r"(a7), "r"(b.z), "r"(b.w));
            }
            if ((lane & 3) == 0) {
                const int g = lane >> 2;
                const int r = tile * 16 + g;
                float2 lo = make_float2(d0[0] + d0[1] + d0[2] + d0[3],
                                        d1[0] + d1[1] + d1[2] + d1[3]);
                float2 hi = make_float2(d2[0] + d2[1] + d2[2] + d2[3],
                                        d3[0] + d3[1] + d3[2] + d3[3]);
                if (half == 0) {
                    *(float2*)&gresA[r][0]     = lo;
                    *(float2*)&gresA[r + 8][0] = hi;
                } else {
                    *(float2*)&gresB[r][0]     = lo;
                    *(float2*)&gresB[r + 8][0] = hi;
                }
            }
        }
        __syncthreads();   // both gres banks visible

        // ---- elementwise phase ----
        if (task) {
            const int j4 = jt * 4;
            float gi, gf, gg, go;
            if (!isL1) {
                gi = gresA[j4 + 0][bt] + gresB[j4 + 0][bt] + cw0 + ep0;
                gf = gresA[j4 + 1][bt] + gresB[j4 + 1][bt] + cw1 + ep1;
                gg = gresA[j4 + 2][bt] + gresB[j4 + 2][bt] + cw2 + ep2;
                go = gresA[j4 + 3][bt] + gresB[j4 + 3][bt] + cw3 + ep3;
            } else {
                gi = gresA[j4 + 0][bt] + gresB[j4 + 0][bt]
                   + gresA[48 + j4 + 0][bt] + gresB[48 + j4 + 0][bt] + cw0;
                gf = gresA[j4 + 1][bt] + gresB[j4 + 1][bt]
                   + gresA[48 + j4 + 1][bt] + gresB[48 + j4 + 1][bt] + cw1;
                gg = gresA[j4 + 2][bt] + gresB[j4 + 2][bt]
                   + gresA[48 + j4 + 2][bt] + gresB[48 + j4 + 2][bt] + cw2;
                go = gresA[j4 + 3][bt] + gresB[j4 + 3][bt]
                   + gresA[48 + j4 + 3][bt] + gresB[48 + j4 + 3][bt] + cw3;
            }
            cst = sigap(gf) * cst + sigap(gi) * tanhap(gg);
            float h = sigap(go) * tanhap(cst);
            __half hh = __float2half(h);
            unsigned hw = (unsigned)__half_as_ushort(hh) | (tagC << 16);
            if (!isL1) {
                asm volatile("st.relaxed.gpu.global.u32 [%0], %1;"
                             :: "l"(&d_h0t[sb][bt * H + et]), "r"(hw) : "memory");
            } else {
                asm volatile("st.relaxed.gpu.global.u32 [%0], %1;"
                             :: "l"(&d_h1t[sb][bt * H + et]), "r"(hw) : "memory");
                d_h1h[(size_t)s * (BB * H) + bt * H + et] = hh;
            }
        }
        // no end-of-step sync: next iteration's waitc barrier isolates bp/gres reuse.
    }
}

// ---------------- CE kernels ----------------
#define CE_TPB   256
#define CE_TOK   14
#define CE_SMEM  (CLS * H * sizeof(float))
__global__ void k_ce(const long long* __restrict__ ids,
                     const float* __restrict__ fcw, const float* __restrict__ fcb) {
    extern __shared__ float sfw[];          // [CLS][H]
    __shared__ float slg[8][32];
    const int tid = threadIdx.x, lane = tid & 31, warp = tid >> 5;

    for (int i = tid; i < (CLS * H) / 4; i += CE_TPB)
        *(float4*)(sfw + i * 4) = *(const float4*)(fcw + i * 4);
    __syncthreads();

    for (int pass = 0; pass < 2; ++pass) {
        int lt = warp + pass * 8;
        int m = blockIdx.x * CE_TOK + lt;
        if (lt < CE_TOK && m < TSTEPS * BB) {
            const int b = m & 1, t = m >> 1;
            float hreg[32];
            const __half* hp = d_h1h + (size_t)t * BB * H + b * H;
#pragma unroll
            for (int i = 0; i < 32; ++i) hreg[i] = __half2float(hp[i * 32 + lane]);
            for (int c = 0; c < CLS; ++c) {
                const float* wr = sfw + c * H;
                float s = 0.f;
#pragma unroll
                for (int i = 0; i < 32; ++i) s += wr[i * 32 + lane] * hreg[i];
#pragma unroll
                for (int off = 16; off > 0; off >>= 1)
                    s += __shfl_xor_sync(0xffffffffu, s, off);
                if (lane == 0) slg[warp][c] = s + fcb[c];
            }
            __syncwarp();
            if (lane == 0) {
                float mx = -1e30f;
                for (int c = 0; c < CLS; ++c) mx = fmaxf(mx, slg[warp][c]);
                float se = 0.f;
                for (int c = 0; c < CLS; ++c) se += expf(slg[warp][c] - mx);
                float lse = mx + logf(se);
                int tgt = (int)ids[b * SEQ + t + 1];
                d_nll[m] = lse - slg[warp][tgt];
            }
            __syncwarp();
        }
    }
}

__global__ void k_loss(const float* __restrict__ mask, float* __restrict__ out) {
    __shared__ float s1s[256], s2s[256];
    const int tid = threadIdx.x;
    float sn = 0.f, sm = 0.f;
    for (int i = tid; i < TSTEPS * BB; i += 256) sn += d_nll[i];
    for (int i = tid; i < BB * TSTEPS; i += 256) {
        int b = i / TSTEPS, t = i % TSTEPS;
        sm += mask[b * SEQ + t + 1];
    }
    s1s[tid] = sn; s2s[tid] = sm;
    __syncthreads();
    for (int o = 128; o > 0; o >>= 1) {
        if (tid < o) { s1s[tid] += s1s[tid + o]; s2s[tid] += s2s[tid + o]; }
        __syncthreads();
    }
    if (tid == 0) {
        float ce = s1s[0] / (float)(TSTEPS * BB);
        float masked = ce * s2s[0] / s2s[0];   // matches reference (incl. mask==0 -> NaN)
        out[0] = ce + masked;
    }
}

// ---------------- launch ----------------
extern "C" void kernel_launch(void* const* d_in, const int* in_sizes, int n_in,
                              void* d_out, int out_size) {
    const long long* ids  = (const long long*)d_in[0];
    const float* mask     = (const float*)d_in[1];
    const float* cond     = (const float*)d_in[2];
    const float* emb      = (const float*)d_in[3];
    const float* Wih0     = (const float*)d_in[4];
    const float* Whh0     = (const float*)d_in[5];
    const float* bih0     = (const float*)d_in[6];
    const float* bhh0     = (const float*)d_in[7];
    const float* Wih1     = (const float*)d_in[8];
    const float* Whh1     = (const float*)d_in[9];
    const float* bih1     = (const float*)d_in[10];
    const float* bhh1     = (const float*)d_in[11];
    const float* fcw      = (const float*)d_in[12];
    const float* fcb      = (const float*)d_in[13];

    static bool init = false;
    if (!init) {
        cudaFuncSetAttribute(k_recur, cudaFuncAttributeMaxDynamicSharedMemorySize,
                             (int)SMEM_TOTAL);
        cudaFuncSetAttribute(k_ce, cudaFuncAttributeMaxDynamicSharedMemorySize,
                             (int)CE_SMEM);
        init = true;
    }

    k_reset<<<32, 256>>>();
    k_pre<<<(2 * G4 * 32 + 255) / 256, 256>>>(Wih0, cond, emb, bih0, bhh0, bih1, bhh1);
    k_recur<<<NB, NT, SMEM_TOTAL>>>(ids, Whh0, Wih1, Whh1);
    k_ce<<<(TSTEPS * BB + CE_TOK - 1) / CE_TOK, CE_TPB, CE_SMEM>>>(ids, fcw, fcb);
    k_loss<<<1, 256>>>(mask, (float*)d_out);
}